// round 10
// baseline (speedup 1.0000x reference)
#include <cuda_runtime.h>
#include <cuda_fp16.h>
#include <cstdint>

// Problem constants
#define KDIM  512          // inner K (diagonal A folded into W)
#define NCOLS 8192         // C*S
#define APAD_ROWS 3712     // 29*128 >= 2M=3680

// -------------------- scratch (static device globals) ----------------------
__device__ __half g_Ahi[APAD_ROWS * KDIM];   // PQ fp16  [3712,512]
__device__ __half g_Bhi[NCOLS * KDIM];       // x^T fp16 [8192,512]

// -------------------- small PTX helpers ------------------------------------
__device__ __forceinline__ uint32_t smem_u32(const void* p) {
    uint32_t a;
    asm("{ .reg .u64 t; cvta.to.shared.u64 t, %1; cvt.u32.u64 %0, t; }" : "=r"(a) : "l"(p));
    return a;
}
__device__ __forceinline__ void cp16(uint32_t saddr, const void* g) {
    asm volatile("cp.async.cg.shared.global [%0], [%1], 16;" :: "r"(saddr), "l"(g));
}
__device__ __forceinline__ void cp_commit() {
    asm volatile("cp.async.commit_group;" ::: "memory");
}
template<int N> __device__ __forceinline__ void cp_wait() {
    asm volatile("cp.async.wait_group %0;" :: "n"(N) : "memory");
}
__device__ __forceinline__ void ldsm4(uint32_t* r, uint32_t addr) {
    asm volatile("ldmatrix.sync.aligned.m8n8.x4.shared.b16 {%0,%1,%2,%3}, [%4];"
                 : "=r"(r[0]), "=r"(r[1]), "=r"(r[2]), "=r"(r[3]) : "r"(addr));
}
__device__ __forceinline__ void mma16816(float* c, const uint32_t* a, const uint32_t* b) {
    asm volatile(
        "mma.sync.aligned.m16n8k16.row.col.f32.f16.f16.f32 "
        "{%0,%1,%2,%3}, {%4,%5,%6,%7}, {%8,%9}, {%0,%1,%2,%3};"
        : "+f"(c[0]), "+f"(c[1]), "+f"(c[2]), "+f"(c[3])
        : "r"(a[0]), "r"(a[1]), "r"(a[2]), "r"(a[3]), "r"(b[0]), "r"(b[1]));
}

// ---------------------------------------------------------------------------
// Combined prep kernel (unchanged from round 9):
//   blocks [0, NB_XT):             xT tiles (64k x 32n)
//   blocks [NB_XT, NB_XT+NB_FOLD): fold + W output + A pad zeroing
// ---------------------------------------------------------------------------
#define NB_XT   2048                   // (512/64) * (8192/32)
#define M_CONST 1840
#define FOLD_GRANULES (M_CONST * 128)
#define PAD_GRANULES  ((APAD_ROWS - 2 * M_CONST) * KDIM / 8)
#define NB_FOLD ((FOLD_GRANULES + PAD_GRANULES + 255) / 256)

__global__ void prep_kernel(const float* __restrict__ x,
                            const float4* __restrict__ Wr4,
                            const float4* __restrict__ Wi4,
                            const float4* __restrict__ ac4,
                            const float4* __restrict__ as4,
                            float4* __restrict__ out4,   // [2M, 256] float4
                            __half* __restrict__ ahi,
                            __half* __restrict__ bhi, int M)
{
    __shared__ float t[64][33];
    const int tid = threadIdx.x;

    if (blockIdx.x < NB_XT) {
        int bx = blockIdx.x;
        int k0 = (bx & 7) * 64;
        int n0 = (bx >> 3) * 32;
        int tx = tid & 31;
        int ty = tid >> 5;
        #pragma unroll
        for (int i = ty; i < 64; i += 8)
            t[i][tx] = x[(size_t)(k0 + i) * NCOLS + n0 + tx];
        __syncthreads();
        #pragma unroll
        for (int i = ty; i < 32; i += 8) {
            __half2 h = __floats2half2_rn(t[2 * tx][i], t[2 * tx + 1][i]);
            *(__half2*)(bhi + (size_t)(n0 + i) * KDIM + k0 + 2 * tx) = h;
        }
        return;
    }

    int idx = (blockIdx.x - NB_XT) * 256 + tid;
    if (idx >= FOLD_GRANULES) {
        int pidx = idx - FOLD_GRANULES;
        if (pidx < PAD_GRANULES)
            ((uint4*)(ahi + (size_t)2 * M * KDIM))[pidx] = make_uint4(0, 0, 0, 0);
        return;
    }
    int j  = idx >> 7;
    int n4 = idx & 127;
    float4 wr = Wr4[idx];
    float4 wi = Wi4[idx];
    float4 c  = ac4[n4];
    float4 s  = as4[n4];

    float4 nwi = make_float4(-wi.x, -wi.y, -wi.z, -wi.w);
    out4[(size_t)j * 256 + n4]             = wr;
    out4[(size_t)j * 256 + 128 + n4]       = nwi;
    out4[(size_t)(j + M) * 256 + n4]       = wi;
    out4[(size_t)(j + M) * 256 + 128 + n4] = wr;

    __half2* pa = (__half2*)(ahi + (size_t)j * KDIM + n4 * 4);
    __half2* qa = (__half2*)(ahi + (size_t)(j + M) * KDIM + n4 * 4);
    pa[0] = __floats2half2_rn(wr.x * c.x - wi.x * s.x, wr.y * c.y - wi.y * s.y);
    pa[1] = __floats2half2_rn(wr.z * c.z - wi.z * s.z, wr.w * c.w - wi.w * s.w);
    qa[0] = __floats2half2_rn(wi.x * c.x + wr.x * s.x, wi.y * c.y + wr.y * s.y);
    qa[1] = __floats2half2_rn(wi.z * c.z + wr.z * s.z, wi.w * c.w + wr.w * s.w);
}

// ---------------------------------------------------------------------------
// GEMM: C[3680,8192] = PQ[3680,512] * x[512,8192]
// CTA 128x128, BK=32, 4 warps (warp tile 64x64 -> 1.0 L1-wf/MMA),
// 5-stage cp.async pipeline, 2 CTAs/SM.
// ---------------------------------------------------------------------------
#define OFF_AH 0
#define OFF_BH 8192
#define STAGE_BYTES 16384
#define NSTAGE 5
#define GEMM_SMEM (NSTAGE * STAGE_BYTES)   // 81920
#define NT_ITERS (KDIM / 32)               // 16

__global__ __launch_bounds__(128, 2)
void czt_gemm_kernel(const __half* __restrict__ Ahi,
                     const __half* __restrict__ Bhi,
                     float* __restrict__ C, int Mrows)
{
    extern __shared__ __align__(1024) char smem[];
    const uint32_t sb = smem_u32(smem);

    const int tid  = threadIdx.x;
    const int lane = tid & 31;
    const int wid  = tid >> 5;      // 0..3
    const int wr   = wid >> 1;      // 0..1  (64-row slabs)
    const int wc   = wid & 1;       // 0..1  (64-col slabs)
    const int bx   = blockIdx.x;    // N tile
    const int by   = blockIdx.y;    // M tile

    const size_t aRowBase = (size_t)by * 128;   // padded, always in-bounds
    const size_t bRowBase = (size_t)bx * 128;

    // cp.async: 4 threads per row (64B contiguous per 4 lanes), 4 row passes
    const int ldR   = tid >> 2;     // 0..31
    const int ldSeg = tid & 3;      // 16B segment within 64B row

    float acc[4][8][4] = {};

    auto issue = [&](int kt) {
        const int stg = kt % NSTAGE;
        const uint32_t sbase = sb + stg * STAGE_BYTES;
        const int k0 = kt * 32;
        #pragma unroll
        for (int it = 0; it < 4; ++it) {
            int r = ldR + it * 32;
            uint32_t so = (uint32_t)(r * 64 + ((ldSeg ^ ((r >> 1) & 3)) << 4));
            size_t ga = (aRowBase + r) * KDIM + k0 + ldSeg * 8;
            size_t gb = (bRowBase + r) * KDIM + k0 + ldSeg * 8;
            cp16(sbase + OFF_AH + so, Ahi + ga);
            cp16(sbase + OFF_BH + so, Bhi + gb);
        }
        cp_commit();
    };

    issue(0);
    issue(1);
    issue(2);
    issue(3);

    // ldmatrix per-lane address components (CTA-tile-relative)
    const int aR   = wr * 64 + (lane & 15);                       // + mt*16
    const int aCs  = (lane >> 4);                                 // + k16*2
    const int bR   = wc * 64 + ((lane >> 4) << 3) + (lane & 7);   // + np*16
    const int bCs  = (lane >> 3) & 1;                             // + k16*2

    for (int kt = 0; kt < NT_ITERS; ++kt) {
        if (kt < NT_ITERS - 3)       cp_wait<3>();
        else if (kt == NT_ITERS - 3) cp_wait<2>();
        else if (kt == NT_ITERS - 2) cp_wait<1>();
        else                         cp_wait<0>();
        __syncthreads();
        if (kt + 4 < NT_ITERS) issue(kt + 4);

        const uint32_t sbase = sb + (kt % NSTAGE) * STAGE_BYTES;

        #pragma unroll
        for (int k16 = 0; k16 < 2; ++k16) {
            uint32_t ah[4][4], bh[16];
            #pragma unroll
            for (int mt = 0; mt < 4; ++mt) {
                int r = aR + mt * 16;
                int cs = aCs + k16 * 2;
                uint32_t so = (uint32_t)(r * 64 + ((cs ^ ((r >> 1) & 3)) << 4));
                ldsm4(ah[mt], sbase + OFF_AH + so);
            }
            #pragma unroll
            for (int np = 0; np < 4; ++np) {
                int r = bR + np * 16;
                int cs = bCs + k16 * 2;
                uint32_t so = (uint32_t)(r * 64 + ((cs ^ ((r >> 1) & 3)) << 4));
                ldsm4(&bh[np * 4], sbase + OFF_BH + so);
            }
            #pragma unroll
            for (int mt = 0; mt < 4; ++mt)
                #pragma unroll
                for (int nt = 0; nt < 8; ++nt)
                    mma16816(acc[mt][nt], ah[mt], &bh[nt * 2]);
        }
    }

    // ---- epilogue ----
    const int rowQ = lane >> 2;
    const int colQ = (lane & 3) * 2;
    #pragma unroll
    for (int mt = 0; mt < 4; ++mt) {
        int row0 = by * 128 + wr * 64 + mt * 16 + rowQ;
        int row1 = row0 + 8;
        #pragma unroll
        for (int nt = 0; nt < 8; ++nt) {
            int col = bx * 128 + wc * 64 + nt * 8 + colQ;
            if (row0 < Mrows)
                *(float2*)(C + (size_t)row0 * NCOLS + col) =
                    make_float2(acc[mt][nt][0], acc[mt][nt][1]);
            if (row1 < Mrows)
                *(float2*)(C + (size_t)row1 * NCOLS + col) =
                    make_float2(acc[mt][nt][2], acc[mt][nt][3]);
        }
    }
}

// ---------------------------------------------------------------------------
// Launch.  Inputs: x, W_real, W_imag, a_cos, a_sin.
// Output: concat( W [2M,2K], X [2M, 8192] ) float32.
// ---------------------------------------------------------------------------
extern "C" void kernel_launch(void* const* d_in, const int* in_sizes, int n_in,
                              void* d_out, int out_size)
{
    const float* x   = (const float*)d_in[0];
    const float* Wr  = (const float*)d_in[1];
    const float* Wi  = (const float*)d_in[2];
    const float* ac  = (const float*)d_in[3];
    const float* as_ = (const float*)d_in[4];

    const int M = in_sizes[1] / KDIM;     // 1840
    const int Mrows = 2 * M;              // 3680

    float* out_w = (float*)d_out;                           // [2M, 2K]
    float* out_x = out_w + (size_t)Mrows * 2 * KDIM;        // [2M, 8192]

    __half *ahi, *bhi;
    cudaGetSymbolAddress((void**)&ahi, g_Ahi);
    cudaGetSymbolAddress((void**)&bhi, g_Bhi);

    // Combined prep: xT -> fp16  AND  W output + PQ fold -> fp16 (+ pad zero)
    prep_kernel<<<NB_XT + NB_FOLD, 256>>>(
        x, (const float4*)Wr, (const float4*)Wi,
        (const float4*)ac, (const float4*)as_,
        (float4*)out_w, ahi, bhi, M);

    // tensor-core GEMM
    {
        cudaFuncSetAttribute(czt_gemm_kernel,
                             cudaFuncAttributeMaxDynamicSharedMemorySize, GEMM_SMEM);
        dim3 grid(NCOLS / 128, (Mrows + 127) / 128);   // (64, 29)
        czt_gemm_kernel<<<grid, 128, GEMM_SMEM>>>(ahi, bhi, out_x, Mrows);
    }
}

// round 11
// speedup vs baseline: 1.0655x; 1.0655x over previous
#include <cuda_runtime.h>
#include <cuda_fp16.h>
#include <cstdint>

// Problem constants
#define KDIM  512          // inner K (diagonal A folded into W)
#define NCOLS 8192         // C*S
#define APAD_ROWS 3712     // 29*128 >= 2M=3680

// -------------------- scratch (static device globals) ----------------------
__device__ __half g_Ahi[APAD_ROWS * KDIM];   // PQ fp16  [3712,512]
__device__ __half g_Bhi[NCOLS * KDIM];       // x^T fp16 [8192,512]

// -------------------- small PTX helpers ------------------------------------
__device__ __forceinline__ uint32_t smem_u32(const void* p) {
    uint32_t a;
    asm("{ .reg .u64 t; cvta.to.shared.u64 t, %1; cvt.u32.u64 %0, t; }" : "=r"(a) : "l"(p));
    return a;
}
__device__ __forceinline__ void cp16(uint32_t saddr, const void* g) {
    asm volatile("cp.async.cg.shared.global [%0], [%1], 16;" :: "r"(saddr), "l"(g));
}
__device__ __forceinline__ void cp_commit() {
    asm volatile("cp.async.commit_group;" ::: "memory");
}
template<int N> __device__ __forceinline__ void cp_wait() {
    asm volatile("cp.async.wait_group %0;" :: "n"(N) : "memory");
}
__device__ __forceinline__ void ldsm4(uint32_t* r, uint32_t addr) {
    asm volatile("ldmatrix.sync.aligned.m8n8.x4.shared.b16 {%0,%1,%2,%3}, [%4];"
                 : "=r"(r[0]), "=r"(r[1]), "=r"(r[2]), "=r"(r[3]) : "r"(addr));
}
__device__ __forceinline__ void mma16816(float* c, const uint32_t* a, const uint32_t* b) {
    asm volatile(
        "mma.sync.aligned.m16n8k16.row.col.f32.f16.f16.f32 "
        "{%0,%1,%2,%3}, {%4,%5,%6,%7}, {%8,%9}, {%0,%1,%2,%3};"
        : "+f"(c[0]), "+f"(c[1]), "+f"(c[2]), "+f"(c[3])
        : "r"(a[0]), "r"(a[1]), "r"(a[2]), "r"(a[3]), "r"(b[0]), "r"(b[1]));
}

// ---------------------------------------------------------------------------
// Combined prep kernel (unchanged, proven ~10 us):
//   blocks [0, NB_XT):             xT tiles (64k x 32n)
//   blocks [NB_XT, NB_XT+NB_FOLD): fold + W output + A pad zeroing
// ---------------------------------------------------------------------------
#define NB_XT   2048                   // (512/64) * (8192/32)
#define M_CONST 1840
#define FOLD_GRANULES (M_CONST * 128)
#define PAD_GRANULES  ((APAD_ROWS - 2 * M_CONST) * KDIM / 8)
#define NB_FOLD ((FOLD_GRANULES + PAD_GRANULES + 255) / 256)

__global__ void prep_kernel(const float* __restrict__ x,
                            const float4* __restrict__ Wr4,
                            const float4* __restrict__ Wi4,
                            const float4* __restrict__ ac4,
                            const float4* __restrict__ as4,
                            float4* __restrict__ out4,   // [2M, 256] float4
                            __half* __restrict__ ahi,
                            __half* __restrict__ bhi, int M)
{
    __shared__ float t[64][33];
    const int tid = threadIdx.x;

    if (blockIdx.x < NB_XT) {
        int bx = blockIdx.x;
        int k0 = (bx & 7) * 64;
        int n0 = (bx >> 3) * 32;
        int tx = tid & 31;
        int ty = tid >> 5;
        #pragma unroll
        for (int i = ty; i < 64; i += 8)
            t[i][tx] = x[(size_t)(k0 + i) * NCOLS + n0 + tx];
        __syncthreads();
        #pragma unroll
        for (int i = ty; i < 32; i += 8) {
            __half2 h = __floats2half2_rn(t[2 * tx][i], t[2 * tx + 1][i]);
            *(__half2*)(bhi + (size_t)(n0 + i) * KDIM + k0 + 2 * tx) = h;
        }
        return;
    }

    int idx = (blockIdx.x - NB_XT) * 256 + tid;
    if (idx >= FOLD_GRANULES) {
        int pidx = idx - FOLD_GRANULES;
        if (pidx < PAD_GRANULES)
            ((uint4*)(ahi + (size_t)2 * M * KDIM))[pidx] = make_uint4(0, 0, 0, 0);
        return;
    }
    int j  = idx >> 7;
    int n4 = idx & 127;
    float4 wr = Wr4[idx];
    float4 wi = Wi4[idx];
    float4 c  = ac4[n4];
    float4 s  = as4[n4];

    float4 nwi = make_float4(-wi.x, -wi.y, -wi.z, -wi.w);
    out4[(size_t)j * 256 + n4]             = wr;
    out4[(size_t)j * 256 + 128 + n4]       = nwi;
    out4[(size_t)(j + M) * 256 + n4]       = wi;
    out4[(size_t)(j + M) * 256 + 128 + n4] = wr;

    __half2* pa = (__half2*)(ahi + (size_t)j * KDIM + n4 * 4);
    __half2* qa = (__half2*)(ahi + (size_t)(j + M) * KDIM + n4 * 4);
    pa[0] = __floats2half2_rn(wr.x * c.x - wi.x * s.x, wr.y * c.y - wi.y * s.y);
    pa[1] = __floats2half2_rn(wr.z * c.z - wi.z * s.z, wr.w * c.w - wi.w * s.w);
    qa[0] = __floats2half2_rn(wi.x * c.x + wr.x * s.x, wi.y * c.y + wr.y * s.y);
    qa[1] = __floats2half2_rn(wi.z * c.z + wr.z * s.z, wi.w * c.w + wr.w * s.w);
}

// ---------------------------------------------------------------------------
// GEMM (round-9 structure): C[3680,8192] = PQ[3680,512] * x[512,8192]
// CTA 128x128, BK=32, 8 warps (warp tile 64x32), 6-stage cp.async pipeline,
// PAIRED iterations: one __syncthreads per TWO k-chunks (8 barriers total).
// Write stages kt+4,kt+5 never alias read stages kt,kt+1 (mod 6).
// ---------------------------------------------------------------------------
#define OFF_AH 0
#define OFF_BH 8192
#define STAGE_BYTES 16384
#define NSTAGE 6
#define GEMM_SMEM (NSTAGE * STAGE_BYTES)   // 98304
#define NT_ITERS (KDIM / 32)               // 16

__global__ __launch_bounds__(256, 2)
void czt_gemm_kernel(const __half* __restrict__ Ahi,
                     const __half* __restrict__ Bhi,
                     float* __restrict__ C, int Mrows)
{
    extern __shared__ __align__(1024) char smem[];
    const uint32_t sb = smem_u32(smem);

    const int tid  = threadIdx.x;
    const int lane = tid & 31;
    const int wid  = tid >> 5;
    const int wr   = wid >> 2;      // 0..1  (64-row slabs)
    const int wc   = wid & 3;       // 0..3  (32-col slabs)
    const int bx   = blockIdx.x;    // N tile
    const int by   = blockIdx.y;    // M tile

    const size_t aRowBase = (size_t)by * 128;   // padded, always in-bounds
    const size_t bRowBase = (size_t)bx * 128;

    const int ldR   = tid >> 2;     // 0..63
    const int ldSeg = tid & 3;      // 16B segment within 64B row

    float acc[4][4][4] = {};

    auto issue = [&](int kt) {
        const int stg = kt % NSTAGE;
        const uint32_t sbase = sb + stg * STAGE_BYTES;
        const int k0 = kt * 32;
        #pragma unroll
        for (int it = 0; it < 2; ++it) {
            int r = ldR + it * 64;
            uint32_t so = (uint32_t)(r * 64 + ((ldSeg ^ ((r >> 1) & 3)) << 4));
            size_t ga = (aRowBase + r) * KDIM + k0 + ldSeg * 8;
            size_t gb = (bRowBase + r) * KDIM + k0 + ldSeg * 8;
            cp16(sbase + OFF_AH + so, Ahi + ga);
            cp16(sbase + OFF_BH + so, Bhi + gb);
        }
        cp_commit();
    };

    issue(0);
    issue(1);
    issue(2);
    issue(3);

    // ldmatrix per-lane address components (CTA-tile-relative)
    const int aR   = wr * 64 + (lane & 15);                       // + mt*16
    const int aCs  = (lane >> 4);                                 // + k16*2
    const int bR   = wc * 32 + ((lane >> 4) << 3) + (lane & 7);   // + np*16
    const int bCs  = (lane >> 3) & 1;                             // + k16*2

    // One mma block over a given stage base and k16 index
    auto mma_block = [&](uint32_t sbase, int k16) {
        uint32_t ah[4][4], bh[8];
        #pragma unroll
        for (int mt = 0; mt < 4; ++mt) {
            int r = aR + mt * 16;
            int cs = aCs + k16 * 2;
            uint32_t so = (uint32_t)(r * 64 + ((cs ^ ((r >> 1) & 3)) << 4));
            ldsm4(ah[mt], sbase + OFF_AH + so);
        }
        #pragma unroll
        for (int np = 0; np < 2; ++np) {
            int r = bR + np * 16;
            int cs = bCs + k16 * 2;
            uint32_t so = (uint32_t)(r * 64 + ((cs ^ ((r >> 1) & 3)) << 4));
            ldsm4(&bh[np * 4], sbase + OFF_BH + so);
        }
        #pragma unroll
        for (int mt = 0; mt < 4; ++mt)
            #pragma unroll
            for (int nt = 0; nt < 4; ++nt)
                mma16816(acc[mt][nt], ah[mt], &bh[nt * 2]);
    };

    #pragma unroll
    for (int kt = 0; kt < NT_ITERS; kt += 2) {
        // stages kt..min(kt+3,15) are in flight; need kt and kt+1 complete.
        if (kt < NT_ITERS - 4)       cp_wait<2>();
        else if (kt == NT_ITERS - 4) cp_wait<2>();
        else                         cp_wait<0>();   // kt == 14: all done
        __syncthreads();
        if (kt + 4 < NT_ITERS) issue(kt + 4);
        if (kt + 5 < NT_ITERS) issue(kt + 5);

        const uint32_t sb0 = sb + ((kt)     % NSTAGE) * STAGE_BYTES;
        const uint32_t sb1 = sb + ((kt + 1) % NSTAGE) * STAGE_BYTES;
        mma_block(sb0, 0);
        mma_block(sb0, 1);
        mma_block(sb1, 0);
        mma_block(sb1, 1);
    }

    // ---- epilogue ----
    const int rowQ = lane >> 2;
    const int colQ = (lane & 3) * 2;
    #pragma unroll
    for (int mt = 0; mt < 4; ++mt) {
        int row0 = by * 128 + wr * 64 + mt * 16 + rowQ;
        int row1 = row0 + 8;
        #pragma unroll
        for (int nt = 0; nt < 4; ++nt) {
            int col = bx * 128 + wc * 32 + nt * 8 + colQ;
            if (row0 < Mrows)
                *(float2*)(C + (size_t)row0 * NCOLS + col) =
                    make_float2(acc[mt][nt][0], acc[mt][nt][1]);
            if (row1 < Mrows)
                *(float2*)(C + (size_t)row1 * NCOLS + col) =
                    make_float2(acc[mt][nt][2], acc[mt][nt][3]);
        }
    }
}

// ---------------------------------------------------------------------------
// Launch.  Inputs: x, W_real, W_imag, a_cos, a_sin.
// Output: concat( W [2M,2K], X [2M, 8192] ) float32.
// ---------------------------------------------------------------------------
extern "C" void kernel_launch(void* const* d_in, const int* in_sizes, int n_in,
                              void* d_out, int out_size)
{
    const float* x   = (const float*)d_in[0];
    const float* Wr  = (const float*)d_in[1];
    const float* Wi  = (const float*)d_in[2];
    const float* ac  = (const float*)d_in[3];
    const float* as_ = (const float*)d_in[4];

    const int M = in_sizes[1] / KDIM;     // 1840
    const int Mrows = 2 * M;              // 3680

    float* out_w = (float*)d_out;                           // [2M, 2K]
    float* out_x = out_w + (size_t)Mrows * 2 * KDIM;        // [2M, 8192]

    __half *ahi, *bhi;
    cudaGetSymbolAddress((void**)&ahi, g_Ahi);
    cudaGetSymbolAddress((void**)&bhi, g_Bhi);

    // Combined prep: xT -> fp16  AND  W output + PQ fold -> fp16 (+ pad zero)
    prep_kernel<<<NB_XT + NB_FOLD, 256>>>(
        x, (const float4*)Wr, (const float4*)Wi,
        (const float4*)ac, (const float4*)as_,
        (float4*)out_w, ahi, bhi, M);

    // tensor-core GEMM
    {
        cudaFuncSetAttribute(czt_gemm_kernel,
                             cudaFuncAttributeMaxDynamicSharedMemorySize, GEMM_SMEM);
        dim3 grid(NCOLS / 128, (Mrows + 127) / 128);   // (64, 29)
        czt_gemm_kernel<<<grid, 256, GEMM_SMEM>>>(ahi, bhi, out_x, Mrows);
    }
}

// round 12
// speedup vs baseline: 1.0901x; 1.0231x over previous
#include <cuda_runtime.h>
#include <cuda_fp16.h>
#include <cstdint>

// Problem constants
#define KDIM  512          // inner K (diagonal A folded into W)
#define NCOLS 8192         // C*S
#define APAD_ROWS 3712     // 29*128 >= 2M=3680

// -------------------- scratch (static device globals) ----------------------
__device__ __half g_Ahi[APAD_ROWS * KDIM];   // PQ fp16  [3712,512]
__device__ __half g_Bhi[NCOLS * KDIM];       // x^T fp16 [8192,512]

// -------------------- small PTX helpers ------------------------------------
__device__ __forceinline__ uint32_t smem_u32(const void* p) {
    uint32_t a;
    asm("{ .reg .u64 t; cvta.to.shared.u64 t, %1; cvt.u32.u64 %0, t; }" : "=r"(a) : "l"(p));
    return a;
}
__device__ __forceinline__ void cp16(uint32_t saddr, const void* g) {
    asm volatile("cp.async.cg.shared.global [%0], [%1], 16;" :: "r"(saddr), "l"(g));
}
__device__ __forceinline__ void cp_commit() {
    asm volatile("cp.async.commit_group;" ::: "memory");
}
template<int N> __device__ __forceinline__ void cp_wait() {
    asm volatile("cp.async.wait_group %0;" :: "n"(N) : "memory");
}
__device__ __forceinline__ void ldsm4(uint32_t* r, uint32_t addr) {
    asm volatile("ldmatrix.sync.aligned.m8n8.x4.shared.b16 {%0,%1,%2,%3}, [%4];"
                 : "=r"(r[0]), "=r"(r[1]), "=r"(r[2]), "=r"(r[3]) : "r"(addr));
}
__device__ __forceinline__ void mma16816(float* c, const uint32_t* a, const uint32_t* b) {
    asm volatile(
        "mma.sync.aligned.m16n8k16.row.col.f32.f16.f16.f32 "
        "{%0,%1,%2,%3}, {%4,%5,%6,%7}, {%8,%9}, {%0,%1,%2,%3};"
        : "+f"(c[0]), "+f"(c[1]), "+f"(c[2]), "+f"(c[3])
        : "r"(a[0]), "r"(a[1]), "r"(a[2]), "r"(a[3]), "r"(b[0]), "r"(b[1]));
}

// ---------------------------------------------------------------------------
// Prep kernel (lighter: NO W-output writes here):
//   blocks [0, NB_XT):             xT tiles (64k x 32n) -> bhi fp16
//   blocks [NB_XT, NB_XT+NB_FOLD): fold -> ahi fp16, + A pad zeroing
// ---------------------------------------------------------------------------
#define NB_XT   2048                   // (512/64) * (8192/32)
#define M_CONST 1840
#define FOLD_GRANULES (M_CONST * 128)
#define PAD_GRANULES  ((APAD_ROWS - 2 * M_CONST) * KDIM / 8)
#define NB_FOLD ((FOLD_GRANULES + PAD_GRANULES + 255) / 256)

__global__ void prep_kernel(const float* __restrict__ x,
                            const float4* __restrict__ Wr4,
                            const float4* __restrict__ Wi4,
                            const float4* __restrict__ ac4,
                            const float4* __restrict__ as4,
                            __half* __restrict__ ahi,
                            __half* __restrict__ bhi, int M)
{
    __shared__ float t[64][33];
    const int tid = threadIdx.x;

    if (blockIdx.x < NB_XT) {
        int bx = blockIdx.x;
        int k0 = (bx & 7) * 64;
        int n0 = (bx >> 3) * 32;
        int tx = tid & 31;
        int ty = tid >> 5;
        #pragma unroll
        for (int i = ty; i < 64; i += 8)
            t[i][tx] = x[(size_t)(k0 + i) * NCOLS + n0 + tx];
        __syncthreads();
        #pragma unroll
        for (int i = ty; i < 32; i += 8) {
            __half2 h = __floats2half2_rn(t[2 * tx][i], t[2 * tx + 1][i]);
            *(__half2*)(bhi + (size_t)(n0 + i) * KDIM + k0 + 2 * tx) = h;
        }
        return;
    }

    int idx = (blockIdx.x - NB_XT) * 256 + tid;
    if (idx >= FOLD_GRANULES) {
        int pidx = idx - FOLD_GRANULES;
        if (pidx < PAD_GRANULES)
            ((uint4*)(ahi + (size_t)2 * M * KDIM))[pidx] = make_uint4(0, 0, 0, 0);
        return;
    }
    int j  = idx >> 7;
    int n4 = idx & 127;
    float4 wr = Wr4[idx];
    float4 wi = Wi4[idx];
    float4 c  = ac4[n4];
    float4 s  = as4[n4];

    __half2* pa = (__half2*)(ahi + (size_t)j * KDIM + n4 * 4);
    __half2* qa = (__half2*)(ahi + (size_t)(j + M) * KDIM + n4 * 4);
    pa[0] = __floats2half2_rn(wr.x * c.x - wi.x * s.x, wr.y * c.y - wi.y * s.y);
    pa[1] = __floats2half2_rn(wr.z * c.z - wi.z * s.z, wr.w * c.w - wi.w * s.w);
    qa[0] = __floats2half2_rn(wi.x * c.x + wr.x * s.x, wi.y * c.y + wr.y * s.y);
    qa[1] = __floats2half2_rn(wi.z * c.z + wr.z * s.z, wi.w * c.w + wr.w * s.w);
}

// ---------------------------------------------------------------------------
// GEMM (round-9 proven core) + W-writer tail CTAs.
//   blockIdx.y < 29 : GEMM 128x128 tile, BK=32, 8 warps, 5-stage cp.async
//   blockIdx.y == 29: pure-memory W-output writer (rides idle DRAM in the
//                     GEMM's tail wave; 64 blocks grid-stride over Wr/Wi)
// ---------------------------------------------------------------------------
#define OFF_AH 0
#define OFF_BH 8192
#define STAGE_BYTES 16384
#define NSTAGE 5
#define GEMM_SMEM (NSTAGE * STAGE_BYTES)   // 81920
#define NT_ITERS (KDIM / 32)               // 16

__global__ __launch_bounds__(256, 2)
void czt_gemm_kernel(const __half* __restrict__ Ahi,
                     const __half* __restrict__ Bhi,
                     float* __restrict__ C,
                     const float4* __restrict__ Wr4,
                     const float4* __restrict__ Wi4,
                     float4* __restrict__ out4,
                     int Mrows)
{
    const int tid = threadIdx.x;
    const int bx  = blockIdx.x;
    const int by  = blockIdx.y;

    if (by == 29) {
        // ---- W output writer: [[Wr,-Wi],[Wi,Wr]] with hardtanh ----
        const int M = Mrows >> 1;
        const int stride = 64 * 256;
        for (int idx = bx * 256 + tid; idx < M * 128; idx += stride) {
            int j  = idx >> 7;
            int n4 = idx & 127;
            float4 wr = Wr4[idx];
            float4 wi = Wi4[idx];
            wr.x = fminf(1.f, fmaxf(-1.f, wr.x)); wr.y = fminf(1.f, fmaxf(-1.f, wr.y));
            wr.z = fminf(1.f, fmaxf(-1.f, wr.z)); wr.w = fminf(1.f, fmaxf(-1.f, wr.w));
            wi.x = fminf(1.f, fmaxf(-1.f, wi.x)); wi.y = fminf(1.f, fmaxf(-1.f, wi.y));
            wi.z = fminf(1.f, fmaxf(-1.f, wi.z)); wi.w = fminf(1.f, fmaxf(-1.f, wi.w));
            float4 nwi = make_float4(-wi.x, -wi.y, -wi.z, -wi.w);
            out4[(size_t)j * 256 + n4]             = wr;
            out4[(size_t)j * 256 + 128 + n4]       = nwi;
            out4[(size_t)(j + M) * 256 + n4]       = wi;
            out4[(size_t)(j + M) * 256 + 128 + n4] = wr;
        }
        return;
    }

    extern __shared__ __align__(1024) char smem[];
    const uint32_t sb = smem_u32(smem);

    const int lane = tid & 31;
    const int wid  = tid >> 5;
    const int wr   = wid >> 2;      // 0..1  (64-row slabs)
    const int wc   = wid & 3;       // 0..3  (32-col slabs)

    const size_t aRowBase = (size_t)by * 128;   // padded, always in-bounds
    const size_t bRowBase = (size_t)bx * 128;

    const int ldR   = tid >> 2;     // 0..63
    const int ldSeg = tid & 3;      // 16B segment within 64B row

    float acc[4][4][4] = {};

    auto issue = [&](int kt) {
        const int stg = kt % NSTAGE;
        const uint32_t sbase = sb + stg * STAGE_BYTES;
        const int k0 = kt * 32;
        #pragma unroll
        for (int it = 0; it < 2; ++it) {
            int r = ldR + it * 64;
            uint32_t so = (uint32_t)(r * 64 + ((ldSeg ^ ((r >> 1) & 3)) << 4));
            size_t ga = (aRowBase + r) * KDIM + k0 + ldSeg * 8;
            size_t gb = (bRowBase + r) * KDIM + k0 + ldSeg * 8;
            cp16(sbase + OFF_AH + so, Ahi + ga);
            cp16(sbase + OFF_BH + so, Bhi + gb);
        }
        cp_commit();
    };

    issue(0);
    issue(1);
    issue(2);
    issue(3);

    // ldmatrix per-lane address components (CTA-tile-relative)
    const int aR   = wr * 64 + (lane & 15);                       // + mt*16
    const int aCs  = (lane >> 4);                                 // + k16*2
    const int bR   = wc * 32 + ((lane >> 4) << 3) + (lane & 7);   // + np*16
    const int bCs  = (lane >> 3) & 1;                             // + k16*2

    for (int kt = 0; kt < NT_ITERS; ++kt) {
        if (kt < NT_ITERS - 3)       cp_wait<3>();
        else if (kt == NT_ITERS - 3) cp_wait<2>();
        else if (kt == NT_ITERS - 2) cp_wait<1>();
        else                         cp_wait<0>();
        __syncthreads();
        if (kt + 4 < NT_ITERS) issue(kt + 4);

        const uint32_t sbase = sb + (kt % NSTAGE) * STAGE_BYTES;

        #pragma unroll
        for (int k16 = 0; k16 < 2; ++k16) {
            uint32_t ah[4][4], bh[8];
            #pragma unroll
            for (int mt = 0; mt < 4; ++mt) {
                int r = aR + mt * 16;
                int cs = aCs + k16 * 2;
                uint32_t so = (uint32_t)(r * 64 + ((cs ^ ((r >> 1) & 3)) << 4));
                ldsm4(ah[mt], sbase + OFF_AH + so);
            }
            #pragma unroll
            for (int np = 0; np < 2; ++np) {
                int r = bR + np * 16;
                int cs = bCs + k16 * 2;
                uint32_t so = (uint32_t)(r * 64 + ((cs ^ ((r >> 1) & 3)) << 4));
                ldsm4(&bh[np * 4], sbase + OFF_BH + so);
            }
            #pragma unroll
            for (int mt = 0; mt < 4; ++mt)
                #pragma unroll
                for (int nt = 0; nt < 4; ++nt)
                    mma16816(acc[mt][nt], ah[mt], &bh[nt * 2]);
        }
    }

    // ---- epilogue ----
    const int rowQ = lane >> 2;
    const int colQ = (lane & 3) * 2;
    #pragma unroll
    for (int mt = 0; mt < 4; ++mt) {
        int row0 = by * 128 + wr * 64 + mt * 16 + rowQ;
        int row1 = row0 + 8;
        #pragma unroll
        for (int nt = 0; nt < 4; ++nt) {
            int col = bx * 128 + wc * 32 + nt * 8 + colQ;
            if (row0 < Mrows)
                *(float2*)(C + (size_t)row0 * NCOLS + col) =
                    make_float2(acc[mt][nt][0], acc[mt][nt][1]);
            if (row1 < Mrows)
                *(float2*)(C + (size_t)row1 * NCOLS + col) =
                    make_float2(acc[mt][nt][2], acc[mt][nt][3]);
        }
    }
}

// ---------------------------------------------------------------------------
// Launch.  Inputs: x, W_real, W_imag, a_cos, a_sin.
// Output: concat( W [2M,2K], X [2M, 8192] ) float32.
// ---------------------------------------------------------------------------
extern "C" void kernel_launch(void* const* d_in, const int* in_sizes, int n_in,
                              void* d_out, int out_size)
{
    const float* x   = (const float*)d_in[0];
    const float* Wr  = (const float*)d_in[1];
    const float* Wi  = (const float*)d_in[2];
    const float* ac  = (const float*)d_in[3];
    const float* as_ = (const float*)d_in[4];

    const int M = in_sizes[1] / KDIM;     // 1840
    const int Mrows = 2 * M;              // 3680

    float* out_w = (float*)d_out;                           // [2M, 2K]
    float* out_x = out_w + (size_t)Mrows * 2 * KDIM;        // [2M, 8192]

    __half *ahi, *bhi;
    cudaGetSymbolAddress((void**)&ahi, g_Ahi);
    cudaGetSymbolAddress((void**)&bhi, g_Bhi);

    // Prep: xT -> fp16  AND  PQ fold -> fp16 (+ pad zero). No W writes here.
    prep_kernel<<<NB_XT + NB_FOLD, 256>>>(
        x, (const float4*)Wr, (const float4*)Wi,
        (const float4*)ac, (const float4*)as_,
        ahi, bhi, M);

    // GEMM + W-writer tail row
    {
        cudaFuncSetAttribute(czt_gemm_kernel,
                             cudaFuncAttributeMaxDynamicSharedMemorySize, GEMM_SMEM);
        dim3 grid(NCOLS / 128, 30);   // y: 29 GEMM rows + 1 W-writer row
        czt_gemm_kernel<<<grid, 256, GEMM_SMEM>>>(
            ahi, bhi, out_x,
            (const float4*)Wr, (const float4*)Wi, (float4*)out_w,
            Mrows);
    }
}